// round 16
// baseline (speedup 1.0000x reference)
#include <cuda_runtime.h>
#include <cstdint>

#define BATCH 8
#define HW 256
#define KK 13
#define HO 244    // 256 - 13 + 1

// padded intermediate geometry: pixel (y,x) at [y+2][x+9], rows 268, stride 280
#define PH 268
#define PW 280
#define PSZ (PH * PW)
#define HALO_PER_PLANE 9504

// ---- scratch (__device__ globals; no allocations allowed) ----
static __device__ float g_h1[(size_t)BATCH * 64 * PSZ];
static __device__ float g_h2[(size_t)BATCH * 64 * PSZ];
static __device__ float g_w [(size_t)BATCH * 169 * HO * HO];
static __device__ float g_U2[(size_t)16 * 64 * 64];     // W2: [xi][cin][oc]
static __device__ float g_U3[(size_t)16 * 64 * 176];    // W3: [xi][cin][oc pad176]

__device__ __forceinline__ unsigned su(const void* p) {
    return (unsigned)__cvta_generic_to_shared(p);
}
__device__ __forceinline__ void cp16(unsigned dst, const void* src) {
    asm volatile("cp.async.cg.shared.global [%0], [%1], 16;"
                 :: "r"(dst), "l"(src));
}
#define CP_COMMIT() asm volatile("cp.async.commit_group;" ::: "memory")
#define CP_WAIT0()  asm volatile("cp.async.wait_group 0;"  ::: "memory")

// ---------------------------------------------------------------------------
__global__ void zero_halo(float* a, float* b)
{
    long id = (long)blockIdx.x * 256 + threadIdx.x;
    const long half = (long)BATCH * 64 * HALO_PER_PLANE;
    if (id >= 2 * half) return;
    float* buf = (id < half) ? a : b;
    long r = id % half;
    int plane = (int)(r / HALO_PER_PLANE);
    int e = (int)(r % HALO_PER_PLANE);
    int row, col;
    if (e < 560)       { row = e / 280;            col = e % 280; }
    else if (e < 3360) { int f = e - 560; row = 258 + f / 280; col = f % 280; }
    else {
        int f = e - 3360;
        row = 2 + f / 24;
        int c24 = f % 24;
        col = (c24 < 9) ? c24 : 256 + c24;
    }
    buf[(size_t)plane * PSZ + row * PW + col] = 0.f;
}

// ---------------------------------------------------------------------------
// Weight transform: U = G g G^T (F(2x2,3x3)). Layout [xi][cin][ocPad].
__global__ void wino_wtrans(const float* __restrict__ Wt, float* __restrict__ U,
                            int OC, int OCp)
{
    int id = blockIdx.x * 256 + threadIdx.x;
    if (id >= OCp * 64) return;
    int oc = id / 64, c = id % 64;
    float U16[16];
    if (oc < OC) {
        const float* g = Wt + ((size_t)oc * 64 + c) * 9;
        float u[4][3];
#pragma unroll
        for (int j = 0; j < 3; ++j) {
            float g0 = g[j], g1 = g[3 + j], g2 = g[6 + j];
            u[0][j] = g0;
            u[1][j] = 0.5f * (g0 + g1 + g2);
            u[2][j] = 0.5f * (g0 - g1 + g2);
            u[3][j] = g2;
        }
#pragma unroll
        for (int i = 0; i < 4; ++i) {
            float a = u[i][0], bb = u[i][1], cc = u[i][2];
            U16[i * 4 + 0] = a;
            U16[i * 4 + 1] = 0.5f * (a + bb + cc);
            U16[i * 4 + 2] = 0.5f * (a - bb + cc);
            U16[i * 4 + 3] = cc;
        }
    } else {
#pragma unroll
        for (int k = 0; k < 16; ++k) U16[k] = 0.f;
    }
#pragma unroll
    for (int xi = 0; xi < 16; ++xi)
        U[((size_t)xi * 64 + c) * OCp + oc] = U16[xi];
}

// ---------------------------------------------------------------------------
// F(2x2,3x3) Winograd, R10 shape + A/B software pipeline.
// CTA: 16x16 outputs (64 tiles) x 16 oc, 256 threads, 2 CTAs/SM.
// 16 sub-chunks of 4 cin; iteration s runs phaseA(s+1) and phaseB(s) in one
// barrier window. sV double-buffered; sU triple-buffered; sIn double.
// smem floats: sIn 2x3456 | sU 3x2560 | sV 2x4352 (sM aliases both sV bufs)
#define IN_OFF  0
#define U_OFF   6912
#define V_OFF   14592
#define SMEM_FLOATS 23296
#define SMEM_BYTES  (SMEM_FLOATS * 4)

template <bool RELU>
__global__ void __launch_bounds__(256, 2) wino_conv(
    const float* __restrict__ in,
    const float* __restrict__ Ug, const float* __restrict__ bias,
    float* __restrict__ out, int outH, int outW,
    size_t outPlane, int outRowStr, int outYOff, int outXOff,
    int inOff, int OC, int ocGroups, int OCp)
{
    extern __shared__ float smf[];
    float* sInBuf[2] = { smf + IN_OFF, smf + IN_OFF + 3456 };
    float* sUBuf [3] = { smf + U_OFF, smf + U_OFF + 2560, smf + U_OFF + 5120 };
    float* sVBuf [2] = { smf + V_OFF, smf + V_OFF + 4352 };
    float* sM = smf + V_OFF;   // phase C alias: (ocl*64 + tile)*17 + xi (8704)

    const int tid = threadIdx.x;
    const int xi  = tid & 15;
    const int ocg = (tid >> 4) & 1;
    const int tg  = tid >> 5;

    const int b  = blockIdx.z / ocGroups;
    const int og = blockIdx.z % ocGroups;
    const int ocBase = og * 16;
    const int x0 = blockIdx.x * 16, y0 = blockIdx.y * 16;

    const int delta   = (inOff + 8) & 3;
    const int colBase = x0 + ((inOff + 8) & ~3);
    const int rowBase = y0 + inOff + 1;
    const float* inB = in + (size_t)b * 64 * PSZ;

    // phase-A mapping: 1 item per thread per sub-chunk: (c4 = tid>>6, tile)
    const int paC   = tid >> 6;          // 0..3
    const int paT   = tid & 63;
    const int paSrcB = paC * 432 + (paT >> 3) * 48 + (paT & 7) * 2 + delta;

    float acc[8][8];
#pragma unroll
    for (int o = 0; o < 8; ++o)
#pragma unroll
        for (int t = 0; t < 8; ++t) acc[o][t] = 0.f;

    // ---- async stage of one 8-cin group ----
    auto stage = [&](int G) {
        float* sInD = sInBuf[G & 1];
        float* sUD  = sUBuf[G % 3];
        int c0 = G * 8;
#pragma unroll
        for (int k = 0; k < 4; ++k) {
            int idx = tid + 256 * k;
            if (idx < 864) {
                int c  = idx / 108;
                int r  = idx - c * 108;
                int ry = r / 6, kk = r - ry * 6;
                cp16(su(sInD + c * 432 + ry * 24 + 4 * kk),
                     inB + ((size_t)(c0 + c) * PH + rowBase + ry) * PW
                         + colBase + 4 * kk);
            }
        }
#pragma unroll
        for (int k = 0; k < 2; ++k) {
            int idx = tid + 256 * k;
            int c  = idx >> 6;
            int r  = idx & 63;
            int x  = r >> 2, q = r & 3;
            cp16(su(sUD + (c * 16 + x) * 20 + 4 * q),
                 Ug + ((size_t)x * 64 + c0 + c) * OCp + ocBase + 4 * q);
        }
        CP_COMMIT();
    };

    // phase A for sub-chunk t (4 cin): sIn group t>>1, half t&1 -> sV[t&1]
    auto phaseA = [&](int t) {
        const float* sInB = sInBuf[(t >> 1) & 1] + (t & 1) * 1728;
        const float2* base2 = (const float2*)(sInB + paSrcB);
        float d[4][4];
#pragma unroll
        for (int r = 0; r < 4; ++r) {
            float2 lo = base2[r * 12];
            float2 hi = base2[r * 12 + 1];
            d[r][0] = lo.x; d[r][1] = lo.y; d[r][2] = hi.x; d[r][3] = hi.y;
        }
        float z[4][4];
#pragma unroll
        for (int s2 = 0; s2 < 4; ++s2) {
            z[0][s2] = d[0][s2] - d[2][s2];
            z[1][s2] = d[1][s2] + d[2][s2];
            z[2][s2] = d[2][s2] - d[1][s2];
            z[3][s2] = d[1][s2] - d[3][s2];
        }
        float* sVb = sVBuf[t & 1];
#pragma unroll
        for (int i = 0; i < 4; ++i) {
            float* dst = sVb + (paC * 16 + i * 4) * 68 + paT;
            dst[0]      = z[i][0] - z[i][2];
            dst[68]     = z[i][1] + z[i][2];
            dst[2 * 68] = z[i][2] - z[i][1];
            dst[3 * 68] = z[i][1] - z[i][3];
        }
    };

    // ---- pipelined mainloop over 16 sub-chunks ----
    stage(0);
    CP_WAIT0();
    __syncthreads();
    stage(1);
    phaseA(0);

#pragma unroll 1
    for (int s = 0; s < 16; ++s) {
        if (s & 1) CP_WAIT0();
        __syncthreads();
        if (s & 1) {
            int G = (s + 3) >> 1;
            if (G <= 7) stage(G);
        }
        if (s < 15) phaseA(s + 1);

        // phase B: sub-chunk s (4 cin) from sV[s&1], U group s>>1
        const float* sVb = sVBuf[s & 1];
        const float* sU  = sUBuf[(s >> 1) % 3] + (s & 1) * 4 * 16 * 20;
#pragma unroll
        for (int c = 0; c < 4; ++c) {
            const float4 v0 = *(const float4*)&sVb[(c * 16 + xi) * 68 + tg * 8];
            const float4 v1 = *(const float4*)&sVb[(c * 16 + xi) * 68 + tg * 8 + 4];
            const float4 u0 = *(const float4*)&sU[(c * 16 + xi) * 20 + ocg * 8];
            const float4 u1 = *(const float4*)&sU[(c * 16 + xi) * 20 + ocg * 8 + 4];
            float vv[8] = { v0.x, v0.y, v0.z, v0.w, v1.x, v1.y, v1.z, v1.w };
            float uu[8] = { u0.x, u0.y, u0.z, u0.w, u1.x, u1.y, u1.z, u1.w };
#pragma unroll
            for (int o = 0; o < 8; ++o)
#pragma unroll
                for (int t = 0; t < 8; ++t)
                    acc[o][t] = fmaf(uu[o], vv[t], acc[o][t]);
        }
    }
    __syncthreads();

    // ---- phase C: Y = A^T M A, two oc halves via sM ----
#pragma unroll 1
    for (int h = 0; h < 2; ++h) {
        if (ocg == h) {
#pragma unroll
            for (int o = 0; o < 8; ++o)
#pragma unroll
                for (int t = 0; t < 8; ++t)
                    sM[(o * 64 + tg * 8 + t) * 17 + xi] = acc[o][t];
        }
        __syncthreads();
        for (int p = tid; p < 512; p += 256) {
            int oc = p >> 6, t = p & 63;
            int ocG = ocBase + h * 8 + oc;
            if (ocG < OC) {
                const float* src = sM + (oc * 64 + t) * 17;
                float m[4][4];
#pragma unroll
                for (int i = 0; i < 4; ++i)
#pragma unroll
                    for (int j = 0; j < 4; ++j) m[i][j] = src[i * 4 + j];
                float s0[4], s1[4];
#pragma unroll
                for (int j = 0; j < 4; ++j) {
                    s0[j] = m[0][j] + m[1][j] + m[2][j];
                    s1[j] = m[1][j] - m[2][j] - m[3][j];
                }
                float bv = bias[ocG];
                float y00 = s0[0] + s0[1] + s0[2] + bv;
                float y01 = s0[1] - s0[2] - s0[3] + bv;
                float y10 = s1[0] + s1[1] + s1[2] + bv;
                float y11 = s1[1] - s1[2] - s1[3] + bv;
                if (RELU) {
                    y00 = fmaxf(y00, 0.f); y01 = fmaxf(y01, 0.f);
                    y10 = fmaxf(y10, 0.f); y11 = fmaxf(y11, 0.f);
                }
                int oy = y0 + (t >> 3) * 2;
                int ox = x0 + (t & 7) * 2;
                float* o0 = out + (size_t)((size_t)b * OC + ocG) * outPlane
                          + (size_t)(oy + outYOff) * outRowStr + ox + outXOff;
                if (oy < outH) {
                    if (ox     < outW) o0[0] = y00;
                    if (ox + 1 < outW) o0[1] = y01;
                }
                if (oy + 1 < outH) {
                    if (ox     < outW) o0[outRowStr]     = y10;
                    if (ox + 1 < outW) o0[outRowStr + 1] = y11;
                }
            }
        }
        __syncthreads();
    }
}

// ---------------------------------------------------------------------------
// conv1 (1 -> 64): direct, register-tiled; writes the PADDED h1 buffer.
template <bool RELU>
__global__ void __launch_bounds__(256) conv1_direct(
    const float* __restrict__ in,
    const float* __restrict__ Wt, const float* __restrict__ bias,
    float* __restrict__ out)
{
    __shared__ float sIn[34][34];
    __shared__ float sW[16][9];

    const int tx = threadIdx.x, ty = threadIdx.y;
    const int tid = ty * 16 + tx;
    const int b  = blockIdx.z >> 2;
    const int og = blockIdx.z & 3;
    const int ocBase = og * 16;
    const int x0 = blockIdx.x * 32, y0 = blockIdx.y * 32;

    float acc[16][4];
#pragma unroll
    for (int o = 0; o < 16; ++o)
#pragma unroll
        for (int p = 0; p < 4; ++p) acc[o][p] = 0.f;

    const float* inB = in + (size_t)b * HW * HW;

    for (int idx = tid; idx < 34 * 34; idx += 256) {
        int ry = idx / 34, rx = idx % 34;
        int iy = y0 + ry - 1, ix = x0 + rx - 1;
        float v = 0.f;
        if (iy >= 0 && iy < HW && ix >= 0 && ix < HW)
            v = inB[(size_t)iy * HW + ix];
        sIn[ry][rx] = v;
    }
    for (int idx = tid; idx < 16 * 9; idx += 256)
        sW[idx / 9][idx % 9] = Wt[(size_t)(ocBase + idx / 9) * 9 + idx % 9];
    __syncthreads();

    float v[4][4];
#pragma unroll
    for (int u = 0; u < 4; ++u)
#pragma unroll
        for (int w = 0; w < 4; ++w)
            v[u][w] = sIn[2 * ty + u][2 * tx + w];
#pragma unroll
    for (int o = 0; o < 16; ++o) {
#pragma unroll
        for (int ky = 0; ky < 3; ++ky)
#pragma unroll
            for (int kx = 0; kx < 3; ++kx) {
                float wv = sW[o][ky * 3 + kx];
                acc[o][0] = fmaf(v[ky    ][kx    ], wv, acc[o][0]);
                acc[o][1] = fmaf(v[ky    ][kx + 1], wv, acc[o][1]);
                acc[o][2] = fmaf(v[ky + 1][kx    ], wv, acc[o][2]);
                acc[o][3] = fmaf(v[ky + 1][kx + 1], wv, acc[o][3]);
            }
    }

    const int ox = x0 + 2 * tx;
#pragma unroll
    for (int o = 0; o < 16; ++o) {
        int oc = ocBase + o;
        float bv = bias[oc];
        float* ob = out + (size_t)((size_t)b * 64 + oc) * PSZ;
#pragma unroll
        for (int py = 0; py < 2; ++py) {
            int oy = y0 + 2 * ty + py;
            float r0 = acc[o][2 * py] + bv;
            float r1 = acc[o][2 * py + 1] + bv;
            if (RELU) { r0 = fmaxf(r0, 0.f); r1 = fmaxf(r1, 0.f); }
            ob[(size_t)(oy + 2) * PW + ox + 9]     = r0;
            ob[(size_t)(oy + 2) * PW + ox + 1 + 9] = r1;
        }
    }
}

// y[b,i,j] = sum_{u,v} x[b, i+u, j+v] * w[b, u*13+v, i, j]
__global__ void __launch_bounds__(256) agg_kernel(
    const float* __restrict__ x, float* __restrict__ y)
{
    int id = blockIdx.x * 256 + threadIdx.x;
    if (id >= BATCH * HO * HO) return;
    int j = id % HO;
    int i = (id / HO) % HO;
    int b = id / (HO * HO);
    const float* xb = x + (size_t)b * HW * HW;
    const float* wb = g_w + (size_t)b * 169 * HO * HO + (size_t)i * HO + j;
    float acc = 0.f;
    for (int u = 0; u < KK; ++u) {
        const float* xr = xb + (size_t)(i + u) * HW + j;
#pragma unroll
        for (int v = 0; v < KK; ++v)
            acc = fmaf(xr[v], wb[(size_t)(u * KK + v) * HO * HO], acc);
    }
    y[id] = acc;
}

extern "C" void kernel_launch(void* const* d_in, const int* in_sizes, int n_in,
                              void* d_out, int out_size)
{
    const float* x  = (const float*)d_in[0];
    const float* W1 = (const float*)d_in[1];
    const float* b1 = (const float*)d_in[2];
    const float* W2 = (const float*)d_in[3];
    const float* b2 = (const float*)d_in[4];
    const float* W3 = (const float*)d_in[5];
    const float* b3 = (const float*)d_in[6];
    float* y = (float*)d_out;

    float *h1, *h2, *w, *U2, *U3;
    cudaGetSymbolAddress((void**)&h1, g_h1);
    cudaGetSymbolAddress((void**)&h2, g_h2);
    cudaGetSymbolAddress((void**)&w,  g_w);
    cudaGetSymbolAddress((void**)&U2, g_U2);
    cudaGetSymbolAddress((void**)&U3, g_U3);

    static int inited = 0;
    if (!inited) {
        cudaFuncSetAttribute(wino_conv<true>,
            cudaFuncAttributeMaxDynamicSharedMemorySize, SMEM_BYTES);
        cudaFuncSetAttribute(wino_conv<false>,
            cudaFuncAttributeMaxDynamicSharedMemorySize, SMEM_BYTES);
        inited = 1;
    }

    long nz = 2L * BATCH * 64 * HALO_PER_PLANE;
    zero_halo<<<(unsigned)((nz + 255) / 256), 256>>>(h1, h2);
    wino_wtrans<<<(64 * 64 + 255) / 256, 256>>>(W2, U2, 64, 64);
    wino_wtrans<<<(176 * 64 + 255) / 256, 256>>>(W3, U3, 169, 176);

    // conv1: 1 -> 64, relu (direct, writes padded h1)
    conv1_direct<true><<<dim3(8, 8, BATCH * 4), dim3(16, 16)>>>(x, W1, b1, h1);

    // conv2: 64 -> 64, relu (pipelined winograd, padded in/out)
    wino_conv<true><<<dim3(16, 16, BATCH * 4), 256, SMEM_BYTES>>>(
        h1, U2, b2, h2, HW, HW, (size_t)PSZ, PW, 2, 9, 0, 64, 4, 64);

    // conv3: 64 -> 169 (pad 176), cropped interior (244x244, +6), unpadded out
    wino_conv<false><<<dim3(16, 16, BATCH * 11), 256, SMEM_BYTES>>>(
        h2, U3, b3, w, HO, HO, (size_t)(HO * HO), HO, 0, 0, 6, 169, 11, 176);

    // final per-pixel 13x13 patch dot-product
    int n = BATCH * HO * HO;
    agg_kernel<<<(n + 255) / 256, 256>>>(x, y);
}

// round 17
// speedup vs baseline: 1.0872x; 1.0872x over previous
#include <cuda_runtime.h>
#include <cstdint>

#define BATCH 8
#define HW 256
#define KK 13
#define HO 244    // 256 - 13 + 1

// padded intermediate geometry: pixel (y,x) at [y+2][x+9], rows 268, stride 280
#define PH 268
#define PW 280
#define PSZ (PH * PW)
#define HALO_PER_PLANE 9504

// ---- scratch (__device__ globals; no allocations allowed) ----
static __device__ float g_h1[(size_t)BATCH * 64 * PSZ];
static __device__ float g_h2[(size_t)BATCH * 64 * PSZ];
static __device__ float g_w [(size_t)BATCH * 169 * HO * HO];
static __device__ float g_U2[(size_t)16 * 64 * 64];     // W2: [xi][cin][oc]
static __device__ float g_U3[(size_t)16 * 64 * 176];    // W3: [xi][cin][oc pad176]

__device__ __forceinline__ unsigned su(const void* p) {
    return (unsigned)__cvta_generic_to_shared(p);
}
__device__ __forceinline__ void cp16(unsigned dst, const void* src) {
    asm volatile("cp.async.cg.shared.global [%0], [%1], 16;"
                 :: "r"(dst), "l"(src));
}
#define CP_COMMIT() asm volatile("cp.async.commit_group;" ::: "memory")
#define CP_WAIT0()  asm volatile("cp.async.wait_group 0;"  ::: "memory")

// ---------------------------------------------------------------------------
__global__ void zero_halo(float* a, float* b)
{
    long id = (long)blockIdx.x * 256 + threadIdx.x;
    const long half = (long)BATCH * 64 * HALO_PER_PLANE;
    if (id >= 2 * half) return;
    float* buf = (id < half) ? a : b;
    long r = id % half;
    int plane = (int)(r / HALO_PER_PLANE);
    int e = (int)(r % HALO_PER_PLANE);
    int row, col;
    if (e < 560)       { row = e / 280;            col = e % 280; }
    else if (e < 3360) { int f = e - 560; row = 258 + f / 280; col = f % 280; }
    else {
        int f = e - 3360;
        row = 2 + f / 24;
        int c24 = f % 24;
        col = (c24 < 9) ? c24 : 256 + c24;
    }
    buf[(size_t)plane * PSZ + row * PW + col] = 0.f;
}

// ---------------------------------------------------------------------------
// Weight transform: U = G g G^T (F(2x2,3x3)). Layout [xi][cin][ocPad].
__global__ void wino_wtrans(const float* __restrict__ Wt, float* __restrict__ U,
                            int OC, int OCp)
{
    int id = blockIdx.x * 256 + threadIdx.x;
    if (id >= OCp * 64) return;
    int oc = id / 64, c = id % 64;
    float U16[16];
    if (oc < OC) {
        const float* g = Wt + ((size_t)oc * 64 + c) * 9;
        float u[4][3];
#pragma unroll
        for (int j = 0; j < 3; ++j) {
            float g0 = g[j], g1 = g[3 + j], g2 = g[6 + j];
            u[0][j] = g0;
            u[1][j] = 0.5f * (g0 + g1 + g2);
            u[2][j] = 0.5f * (g0 - g1 + g2);
            u[3][j] = g2;
        }
#pragma unroll
        for (int i = 0; i < 4; ++i) {
            float a = u[i][0], bb = u[i][1], cc = u[i][2];
            U16[i * 4 + 0] = a;
            U16[i * 4 + 1] = 0.5f * (a + bb + cc);
            U16[i * 4 + 2] = 0.5f * (a - bb + cc);
            U16[i * 4 + 3] = cc;
        }
    } else {
#pragma unroll
        for (int k = 0; k < 16; ++k) U16[k] = 0.f;
    }
#pragma unroll
    for (int xi = 0; xi < 16; ++xi)
        U[((size_t)xi * 64 + c) * OCp + oc] = U16[xi];
}

// ---------------------------------------------------------------------------
// F(2x2,3x3) Winograd — EXACT R10 configuration (best known: 2569 us).
// CTA: 16x16 outputs (64 tiles) x 16 oc, 256 threads, 2 CTAs/SM.
// smem floats: sIn 2x3456 (stride-24 rows) | sU 2x2560 (stride 20) |
//              sV 8704 (stride 68; sM aliases)
#define IN_OFF  0
#define U_OFF   6912
#define V_OFF   12032
#define SMEM_FLOATS 20736
#define SMEM_BYTES  (SMEM_FLOATS * 4)

template <bool RELU>
__global__ void __launch_bounds__(256, 2) wino_conv(
    const float* __restrict__ in,
    const float* __restrict__ Ug, const float* __restrict__ bias,
    float* __restrict__ out, int outH, int outW,
    size_t outPlane, int outRowStr, int outYOff, int outXOff,
    int inOff, int OC, int ocGroups, int OCp)
{
    extern __shared__ float smf[];
    float* sInBuf[2] = { smf + IN_OFF, smf + IN_OFF + 3456 };
    float* sUBuf [2] = { smf + U_OFF,  smf + U_OFF + 2560 };
    float* sV = smf + V_OFF;   // (c*16 + xi)*68 + tile
    float* sM = smf + V_OFF;   // phase C alias: (ocl*64 + tile)*17 + xi

    const int tid = threadIdx.x;
    const int xi  = tid & 15;
    const int ocg = (tid >> 4) & 1;
    const int tg  = tid >> 5;

    const int b  = blockIdx.z / ocGroups;
    const int og = blockIdx.z % ocGroups;
    const int ocBase = og * 16;
    const int x0 = blockIdx.x * 16, y0 = blockIdx.y * 16;

    const int delta   = (inOff + 8) & 3;
    const int colBase = x0 + ((inOff + 8) & ~3);
    const int rowBase = y0 + inOff + 1;
    const float* inB = in + (size_t)b * 64 * PSZ;

    // hoisted phase-A mapping (2 items per thread)
    int paSrc[2], paC16[2], paT[2];
#pragma unroll
    for (int q = 0; q < 2; ++q) {
        int p = tid + 256 * q;
        int c = p >> 6, t = p & 63;
        paSrc[q] = c * 432 + (t >> 3) * 48 + (t & 7) * 2 + delta;
        paC16[q] = c * 16;
        paT[q]   = t;
    }

    float acc[8][8];
#pragma unroll
    for (int j = 0; j < 8; ++j)
#pragma unroll
        for (int t = 0; t < 8; ++t) acc[j][t] = 0.f;

    auto stage = [&](int c0, float* sInD, float* sUD) {
#pragma unroll
        for (int k = 0; k < 4; ++k) {
            int idx = tid + 256 * k;
            if (idx < 864) {
                int c  = idx / 108;
                int r  = idx - c * 108;
                int ry = r / 6, kk = r - ry * 6;
                cp16(su(sInD + c * 432 + ry * 24 + 4 * kk),
                     inB + ((size_t)(c0 + c) * PH + rowBase + ry) * PW
                         + colBase + 4 * kk);
            }
        }
#pragma unroll
        for (int k = 0; k < 2; ++k) {
            int idx = tid + 256 * k;
            int c  = idx >> 6;
            int r  = idx & 63;
            int x  = r >> 2, q = r & 3;
            cp16(su(sUD + (c * 16 + x) * 20 + 4 * q),
                 Ug + ((size_t)x * 64 + c0 + c) * OCp + ocBase + 4 * q);
        }
        CP_COMMIT();
    };

    stage(0, sInBuf[0], sUBuf[0]);

#pragma unroll 1
    for (int ci = 0; ci < 8; ++ci) {
        const int cur = ci & 1;
        float* sIn = sInBuf[cur];
        float* sU  = sUBuf[cur];

        CP_WAIT0();
        __syncthreads();
        if (ci < 7) stage((ci + 1) * 8, sInBuf[cur ^ 1], sUBuf[cur ^ 1]);

        // ---- phase A: V = B^T d B -> sV[(c*16+xi)*68 + tile] ----
#pragma unroll
        for (int q = 0; q < 2; ++q) {
            const float2* base2 = (const float2*)(sIn + paSrc[q]);
            float d[4][4];
#pragma unroll
            for (int r = 0; r < 4; ++r) {
                float2 lo = base2[r * 12];
                float2 hi = base2[r * 12 + 1];
                d[r][0] = lo.x; d[r][1] = lo.y; d[r][2] = hi.x; d[r][3] = hi.y;
            }
            float z[4][4];
#pragma unroll
            for (int s = 0; s < 4; ++s) {
                z[0][s] = d[0][s] - d[2][s];
                z[1][s] = d[1][s] + d[2][s];
                z[2][s] = d[2][s] - d[1][s];
                z[3][s] = d[1][s] - d[3][s];
            }
#pragma unroll
            for (int i = 0; i < 4; ++i) {
                float* dst = sV + (paC16[q] + i * 4) * 68 + paT[q];
                dst[0]      = z[i][0] - z[i][2];
                dst[68]     = z[i][1] + z[i][2];
                dst[2 * 68] = z[i][2] - z[i][1];
                dst[3 * 68] = z[i][1] - z[i][3];
            }
        }
        __syncthreads();

        // ---- phase B: vectorized rank-1 updates per channel ----
#pragma unroll
        for (int c = 0; c < 8; ++c) {
            const float4 v0 = *(const float4*)&sV[(c * 16 + xi) * 68 + tg * 8];
            const float4 v1 = *(const float4*)&sV[(c * 16 + xi) * 68 + tg * 8 + 4];
            const float4 u0 = *(const float4*)&sU[(c * 16 + xi) * 20 + ocg * 8];
            const float4 u1 = *(const float4*)&sU[(c * 16 + xi) * 20 + ocg * 8 + 4];
            float vv[8] = { v0.x, v0.y, v0.z, v0.w, v1.x, v1.y, v1.z, v1.w };
            float uu[8] = { u0.x, u0.y, u0.z, u0.w, u1.x, u1.y, u1.z, u1.w };
#pragma unroll
            for (int j = 0; j < 8; ++j)
#pragma unroll
                for (int t = 0; t < 8; ++t)
                    acc[j][t] = fmaf(uu[j], vv[t], acc[j][t]);
        }
        __syncthreads();
    }

    // ---- phase C: Y = A^T M A, two oc halves via sM ----
#pragma unroll 1
    for (int h = 0; h < 2; ++h) {
        if (ocg == h) {
#pragma unroll
            for (int j = 0; j < 8; ++j)
#pragma unroll
                for (int t = 0; t < 8; ++t)
                    sM[(j * 64 + tg * 8 + t) * 17 + xi] = acc[j][t];
        }
        __syncthreads();
        for (int p = tid; p < 512; p += 256) {
            int oc = p >> 6, t = p & 63;
            int ocG = ocBase + h * 8 + oc;
            if (ocG < OC) {
                const float* src = sM + (oc * 64 + t) * 17;
                float m[4][4];
#pragma unroll
                for (int i = 0; i < 4; ++i)
#pragma unroll
                    for (int j = 0; j < 4; ++j) m[i][j] = src[i * 4 + j];
                float s0[4], s1[4];
#pragma unroll
                for (int j = 0; j < 4; ++j) {
                    s0[j] = m[0][j] + m[1][j] + m[2][j];
                    s1[j] = m[1][j] - m[2][j] - m[3][j];
                }
                float bv = bias[ocG];
                float y00 = s0[0] + s0[1] + s0[2] + bv;
                float y01 = s0[1] - s0[2] - s0[3] + bv;
                float y10 = s1[0] + s1[1] + s1[2] + bv;
                float y11 = s1[1] - s1[2] - s1[3] + bv;
                if (RELU) {
                    y00 = fmaxf(y00, 0.f); y01 = fmaxf(y01, 0.f);
                    y10 = fmaxf(y10, 0.f); y11 = fmaxf(y11, 0.f);
                }
                int oy = y0 + (t >> 3) * 2;
                int ox = x0 + (t & 7) * 2;
                float* o0 = out + (size_t)((size_t)b * OC + ocG) * outPlane
                          + (size_t)(oy + outYOff) * outRowStr + ox + outXOff;
                if (oy < outH) {
                    if (ox     < outW) o0[0] = y00;
                    if (ox + 1 < outW) o0[1] = y01;
                }
                if (oy + 1 < outH) {
                    if (ox     < outW) o0[outRowStr]     = y10;
                    if (ox + 1 < outW) o0[outRowStr + 1] = y11;
                }
            }
        }
        __syncthreads();
    }
}

// ---------------------------------------------------------------------------
// conv1 (1 -> 64): direct; each CTA stages its 34x34 tile ONCE and loops
// over all 4 oc-groups (staging traffic /4, 4x work per CTA).
template <bool RELU>
__global__ void __launch_bounds__(256) conv1_direct(
    const float* __restrict__ in,
    const float* __restrict__ Wt, const float* __restrict__ bias,
    float* __restrict__ out)
{
    __shared__ float sIn[34][34];
    __shared__ float sW[16][9];

    const int tx = threadIdx.x, ty = threadIdx.y;
    const int tid = ty * 16 + tx;
    const int b  = blockIdx.z;
    const int x0 = blockIdx.x * 32, y0 = blockIdx.y * 32;

    const float* inB = in + (size_t)b * HW * HW;

    for (int idx = tid; idx < 34 * 34; idx += 256) {
        int ry = idx / 34, rx = idx % 34;
        int iy = y0 + ry - 1, ix = x0 + rx - 1;
        float v = 0.f;
        if (iy >= 0 && iy < HW && ix >= 0 && ix < HW)
            v = inB[(size_t)iy * HW + ix];
        sIn[ry][rx] = v;
    }
    __syncthreads();

    // input window registers, reused across all oc-groups
    float v[4][4];
#pragma unroll
    for (int u = 0; u < 4; ++u)
#pragma unroll
        for (int w = 0; w < 4; ++w)
            v[u][w] = sIn[2 * ty + u][2 * tx + w];

    const int ox = x0 + 2 * tx;

#pragma unroll 1
    for (int og = 0; og < 4; ++og) {
        const int ocBase = og * 16;
        if (tid < 144)
            sW[tid / 9][tid % 9] = Wt[(size_t)(ocBase + tid / 9) * 9 + tid % 9];
        __syncthreads();

        float acc[16][4];
#pragma unroll
        for (int o = 0; o < 16; ++o)
#pragma unroll
            for (int p = 0; p < 4; ++p) acc[o][p] = 0.f;

#pragma unroll
        for (int o = 0; o < 16; ++o) {
#pragma unroll
            for (int ky = 0; ky < 3; ++ky)
#pragma unroll
                for (int kx = 0; kx < 3; ++kx) {
                    float wv = sW[o][ky * 3 + kx];
                    acc[o][0] = fmaf(v[ky    ][kx    ], wv, acc[o][0]);
                    acc[o][1] = fmaf(v[ky    ][kx + 1], wv, acc[o][1]);
                    acc[o][2] = fmaf(v[ky + 1][kx    ], wv, acc[o][2]);
                    acc[o][3] = fmaf(v[ky + 1][kx + 1], wv, acc[o][3]);
                }
        }

#pragma unroll
        for (int o = 0; o < 16; ++o) {
            int oc = ocBase + o;
            float bv = bias[oc];
            float* ob = out + (size_t)((size_t)b * 64 + oc) * PSZ;
#pragma unroll
            for (int py = 0; py < 2; ++py) {
                int oy = y0 + 2 * ty + py;
                float r0 = acc[o][2 * py] + bv;
                float r1 = acc[o][2 * py + 1] + bv;
                if (RELU) { r0 = fmaxf(r0, 0.f); r1 = fmaxf(r1, 0.f); }
                ob[(size_t)(oy + 2) * PW + ox + 9]     = r0;
                ob[(size_t)(oy + 2) * PW + ox + 1 + 9] = r1;
            }
        }
        __syncthreads();   // protect sW before next group restages
    }
}

// y[b,i,j] = sum_{u,v} x[b, i+u, j+v] * w[b, u*13+v, i, j]
__global__ void __launch_bounds__(256) agg_kernel(
    const float* __restrict__ x, float* __restrict__ y)
{
    int id = blockIdx.x * 256 + threadIdx.x;
    if (id >= BATCH * HO * HO) return;
    int j = id % HO;
    int i = (id / HO) % HO;
    int b = id / (HO * HO);
    const float* xb = x + (size_t)b * HW * HW;
    const float* wb = g_w + (size_t)b * 169 * HO * HO + (size_t)i * HO + j;
    float acc = 0.f;
    for (int u = 0; u < KK; ++u) {
        const float* xr = xb + (size_t)(i + u) * HW + j;
#pragma unroll
        for (int v = 0; v < KK; ++v)
            acc = fmaf(xr[v], wb[(size_t)(u * KK + v) * HO * HO], acc);
    }
    y[id] = acc;
}

extern "C" void kernel_launch(void* const* d_in, const int* in_sizes, int n_in,
                              void* d_out, int out_size)
{
    const float* x  = (const float*)d_in[0];
    const float* W1 = (const float*)d_in[1];
    const float* b1 = (const float*)d_in[2];
    const float* W2 = (const float*)d_in[3];
    const float* b2 = (const float*)d_in[4];
    const float* W3 = (const float*)d_in[5];
    const float* b3 = (const float*)d_in[6];
    float* y = (float*)d_out;

    float *h1, *h2, *w, *U2, *U3;
    cudaGetSymbolAddress((void**)&h1, g_h1);
    cudaGetSymbolAddress((void**)&h2, g_h2);
    cudaGetSymbolAddress((void**)&w,  g_w);
    cudaGetSymbolAddress((void**)&U2, g_U2);
    cudaGetSymbolAddress((void**)&U3, g_U3);

    static int inited = 0;
    if (!inited) {
        cudaFuncSetAttribute(wino_conv<true>,
            cudaFuncAttributeMaxDynamicSharedMemorySize, SMEM_BYTES);
        cudaFuncSetAttribute(wino_conv<false>,
            cudaFuncAttributeMaxDynamicSharedMemorySize, SMEM_BYTES);
        inited = 1;
    }

    long nz = 2L * BATCH * 64 * HALO_PER_PLANE;
    zero_halo<<<(unsigned)((nz + 255) / 256), 256>>>(h1, h2);
    wino_wtrans<<<(64 * 64 + 255) / 256, 256>>>(W2, U2, 64, 64);
    wino_wtrans<<<(176 * 64 + 255) / 256, 256>>>(W3, U3, 169, 176);

    // conv1: 1 -> 64, relu (direct, single staging, 4 oc-groups per CTA)
    conv1_direct<true><<<dim3(8, 8, BATCH), dim3(16, 16)>>>(x, W1, b1, h1);

    // conv2: 64 -> 64, relu (winograd, padded in/out)  — exact R10
    wino_conv<true><<<dim3(16, 16, BATCH * 4), 256, SMEM_BYTES>>>(
        h1, U2, b2, h2, HW, HW, (size_t)PSZ, PW, 2, 9, 0, 64, 4, 64);

    // conv3: 64 -> 169 (pad 176), cropped interior (244x244, +6) — exact R10
    wino_conv<false><<<dim3(16, 16, BATCH * 11), 256, SMEM_BYTES>>>(
        h2, U3, b3, w, HO, HO, (size_t)(HO * HO), HO, 0, 0, 6, 169, 11, 176);

    // final per-pixel 13x13 patch dot-product
    int n = BATCH * HO * HO;
    agg_kernel<<<(n + 255) / 256, 256>>>(x, y);
}